// round 8
// baseline (speedup 1.0000x reference)
#include <cuda_runtime.h>
#include <math.h>

// Inputs (metadata order): y[16M] f32, mu[16M] f32, std[16M] f32, idx[200*100] i32
// Output: 1 x f32 (KL scalar)

#define NUM_SAMPLES 200
#define KDOF 100

// Moments packed in one 8B-aligned struct -> winner reads both with ONE
// ld.acquire.gpu.v2.f32 (single L2 round-trip).
struct __align__(8) Moments { float s1, s2; };
__device__ Moments      g_m = {0.0f, 0.0f};
__device__ unsigned int g_count = 0;

__device__ __forceinline__ void red_release_f32(float* addr, float val) {
    asm volatile("red.release.gpu.global.add.f32 [%0], %1;"
                 :: "l"(addr), "f"(val) : "memory");
}
__device__ __forceinline__ unsigned int ticket_acq_rel(unsigned int* addr) {
    unsigned int old;
    asm volatile("atom.acq_rel.gpu.global.add.u32 %0, [%1], 1;"
                 : "=r"(old) : "l"(addr) : "memory");
    return old;
}
__device__ __forceinline__ float2 ld_acquire_v2(const Moments* addr) {
    float2 v;
    asm volatile("ld.acquire.gpu.global.v2.f32 {%0, %1}, [%2];"
                 : "=f"(v.x), "=f"(v.y) : "l"(addr) : "memory");
    return v;
}

// 200 blocks x 128 threads: one gather triple per thread (best measured
// load-queue shape). Shifted moments folded via release-REDs; last block
// (acq_rel ticket) computes KL. No MEMBARs, no g_q array, minimal tail.
__global__ void __launch_bounds__(128) fused_chi2_kl_kernel(
    const float* __restrict__ y,
    const float* __restrict__ mu,
    const float* __restrict__ sd,
    const int*   __restrict__ idx,
    float*       __restrict__ out)
{
    const int s = blockIdx.x;
    const int t = threadIdx.x;

    // ---- Phase 1: per-sample chi-square statistic ----
    // Chain head: issue idx load immediately.
    int i = 0;
    const bool active = (t < KDOF);
    if (active) i = idx[s * KDOF + t];

    float v = 0.0f;
    if (active) {
        // three independent gathers -> MLP=3 per thread
        const float d = __fdividef(y[i] - mu[i], sd[i]);
        v = d * d;
    }

    #pragma unroll
    for (int o = 16; o > 0; o >>= 1)
        v += __shfl_down_sync(0xFFFFFFFFu, v, o);

    __shared__ float sm[4];
    if ((t & 31) == 0) sm[t >> 5] = v;
    __syncthreads();

    if (t != 0) return;

    // Shifted statistic p = q - K (kills cancellation in the var formula).
    const float p = (sm[0] + sm[1] + sm[2] + sm[3]) - (float)KDOF;

    red_release_f32(&g_m.s1, p);
    red_release_f32(&g_m.s2, p * p);

    if (ticket_acq_rel(&g_count) != NUM_SAMPLES - 1u) return;

    // ---- Phase 2 (single thread, last block to tick): KL ----
    const float2 m = ld_acquire_v2(&g_m);     // one round-trip for both sums

    const float inv_n = 1.0f / (float)NUM_SAMPLES;
    const float dm    = m.x * inv_n;                          // emp_mu - K
    const float var   = (m.y - m.x * m.x * inv_n)
                        * (1.0f / (float)(NUM_SAMPLES - 1));  // unbiased var
    const float two_k = 2.0f * (float)KDOF;

    out[0] = 0.5f * __logf(two_k / var)
           + (var + dm * dm) / (2.0f * two_k)
           - 0.5f;

    // Reset scratch for next graph replay.
    g_m.s1 = 0.0f;
    g_m.s2 = 0.0f;
    g_count = 0;
}

extern "C" void kernel_launch(void* const* d_in, const int* in_sizes, int n_in,
                              void* d_out, int out_size)
{
    const float* y   = (const float*)d_in[0];
    const float* mu  = (const float*)d_in[1];
    const float* sd  = (const float*)d_in[2];
    const int*   idx = (const int*)d_in[3];
    float* out = (float*)d_out;

    fused_chi2_kl_kernel<<<NUM_SAMPLES, 128>>>(y, mu, sd, idx, out);
}